// round 1
// baseline (speedup 1.0000x reference)
#include <cuda_runtime.h>

#define NN 50000
#define NT 256

// ---------------- scratch (static device globals; no allocs) ----------------
__device__ int   g_is64;                 // 1 if edge indices are int64, 0 if int32
__device__ int   g_cnt[6 * NN];          // [2r]=deg_out(src), [2r+1]=deg_in(dst)
__device__ float g_rs [6 * NN];          // rsqrt(max(deg,1))
__device__ float g_h1 [3 * NN * 16];     // per-relation scaled layer-1 features
__device__ float g_m  [3 * NN * 16];     // per-relation aggregation buffers
__device__ float g_s  [3 * NN];          // per-relation scalar layer-2 messages
__device__ float g_o2 [3 * NN];          // per-relation scalar aggregation

// ---------------- dtype detection ----------------
// Indices are in [0, 50000): if stored as int64 (little-endian), every odd
// 32-bit word is 0. If int32, the first 2048 odd words are random indices
// (P(all zero) ~ (1/50000)^2048 == 0).
__global__ void k_detect(const unsigned* __restrict__ p, int n) {
    __shared__ int found;
    if (threadIdx.x == 0) found = 0;
    __syncthreads();
    int f = 0;
    for (int i = threadIdx.x; i < n; i += blockDim.x)
        if (p[2 * i + 1] != 0u) f = 1;
    if (f) atomicOr(&found, 1);
    __syncthreads();
    if (threadIdx.x == 0) g_is64 = found ? 0 : 1;
}

__device__ __forceinline__ int ldidx(const void* __restrict__ p, int i) {
    return g_is64 ? (int)__ldg((const long long*)p + i)
                  : __ldg((const int*)p + i);
}

// ---------------- degrees ----------------
__global__ void k_zero_cnt() {
    int i = blockIdx.x * blockDim.x + threadIdx.x;
    if (i < 6 * NN) g_cnt[i] = 0;
}

__global__ void k_deg(const void* __restrict__ src, const void* __restrict__ dst,
                      int E, int r) {
    int e = blockIdx.x * blockDim.x + threadIdx.x;
    if (e >= E) return;
    atomicAdd(&g_cnt[(2 * r)     * NN + ldidx(src, e)], 1);
    atomicAdd(&g_cnt[(2 * r + 1) * NN + ldidx(dst, e)], 1);
}

__global__ void k_rsqrt() {
    int i = blockIdx.x * blockDim.x + threadIdx.x;
    if (i < 6 * NN) {
        int c = g_cnt[i];
        g_rs[i] = rsqrtf((float)(c > 0 ? c : 1));
    }
}

// ---------------- layer 1: per-node transform (and zero g_m) ----------------
__global__ void k_layer1_node(const float* __restrict__ x, const float* __restrict__ W1) {
    __shared__ float sW[3 * 32 * 16];
    for (int i = threadIdx.x; i < 1536; i += blockDim.x) sW[i] = W1[i];
    __syncthreads();
    int n = blockIdx.x * blockDim.x + threadIdx.x;
    if (n >= NN) return;
    float xv[32];
    #pragma unroll
    for (int j = 0; j < 8; j++) {
        float4 v = __ldg((const float4*)(x + (size_t)n * 32) + j);
        xv[4*j] = v.x; xv[4*j+1] = v.y; xv[4*j+2] = v.z; xv[4*j+3] = v.w;
    }
    #pragma unroll
    for (int r = 0; r < 3; r++) {
        float a = g_rs[(2 * r) * NN + n];
        float y[16];
        #pragma unroll
        for (int f = 0; f < 16; f++) y[f] = 0.f;
        #pragma unroll
        for (int j = 0; j < 32; j++) {
            float xj = xv[j];
            #pragma unroll
            for (int f = 0; f < 16; f++)
                y[f] += xj * sW[r * 512 + j * 16 + f];
        }
        float* hp = &g_h1[(size_t)(r * NN + n) * 16];
        float* mp = &g_m [(size_t)(r * NN + n) * 16];
        #pragma unroll
        for (int f = 0; f < 16; f += 4) {
            *(float4*)(hp + f) = make_float4(a*y[f], a*y[f+1], a*y[f+2], a*y[f+3]);
            *(float4*)(mp + f) = make_float4(0.f, 0.f, 0.f, 0.f);
        }
    }
}

// ---------------- layer 1: edge scatter (16 floats via 4x red.v4) ----------------
__global__ void k_scatter16(const void* __restrict__ src, const void* __restrict__ dst,
                            int E, int rbase) {
    long long t = (long long)blockIdx.x * blockDim.x + threadIdx.x;
    if (t >= (long long)E * 4) return;
    int e = (int)(t >> 2), c = (int)(t & 3);
    int s = ldidx(src, e);
    int d = ldidx(dst, e);
    const float4 v = *(const float4*)&g_h1[(size_t)(rbase + s) * 16 + c * 4];
    float* mp = &g_m[(size_t)(rbase + d) * 16 + c * 4];
    asm volatile("red.global.add.v4.f32 [%0], {%1, %2, %3, %4};"
                 :: "l"(mp), "f"(v.x), "f"(v.y), "f"(v.z), "f"(v.w) : "memory");
}

// ---------------- combine + relu + layer-2 node transform (and zero g_o2) ----
__global__ void k_combine(const float* __restrict__ b1, const float* __restrict__ W2) {
    __shared__ float sW2[48], sb1[48];
    if (threadIdx.x < 48) {
        sW2[threadIdx.x] = W2[threadIdx.x];
        sb1[threadIdx.x] = b1[threadIdx.x];
    }
    __syncthreads();
    int n = blockIdx.x * blockDim.x + threadIdx.x;
    if (n >= NN) return;
    float acc[16];
    #pragma unroll
    for (int f = 0; f < 16; f++) acc[f] = 0.f;
    #pragma unroll
    for (int r = 0; r < 3; r++) {
        float ain = g_rs[(2 * r + 1) * NN + n];
        const float* mp = &g_m[(size_t)(r * NN + n) * 16];
        #pragma unroll
        for (int f = 0; f < 16; f += 4) {
            float4 v = *(const float4*)(mp + f);
            acc[f]   += v.x * ain + sb1[r*16 + f];
            acc[f+1] += v.y * ain + sb1[r*16 + f + 1];
            acc[f+2] += v.z * ain + sb1[r*16 + f + 2];
            acc[f+3] += v.w * ain + sb1[r*16 + f + 3];
        }
    }
    #pragma unroll
    for (int f = 0; f < 16; f++) acc[f] = fmaxf(acc[f], 0.f);
    #pragma unroll
    for (int r = 0; r < 3; r++) {
        float aout = g_rs[(2 * r) * NN + n];
        float dot = 0.f;
        #pragma unroll
        for (int f = 0; f < 16; f++) dot += acc[f] * sW2[r*16 + f];
        g_s [r * NN + n] = aout * dot;
        g_o2[r * NN + n] = 0.f;
    }
}

// ---------------- layer 2: scalar edge scatter ----------------
__global__ void k_scatter1(const void* __restrict__ src, const void* __restrict__ dst,
                           int E, int rbase) {
    int e = blockIdx.x * blockDim.x + threadIdx.x;
    if (e >= E) return;
    float v = g_s[rbase + ldidx(src, e)];
    atomicAdd(&g_o2[rbase + ldidx(dst, e)], v);
}

// ---------------- final ----------------
__global__ void k_final(float* __restrict__ out, const float* __restrict__ b2) {
    int n = blockIdx.x * blockDim.x + threadIdx.x;
    if (n >= NN) return;
    float o = 0.f;
    #pragma unroll
    for (int r = 0; r < 3; r++)
        o += g_o2[r * NN + n] * g_rs[(2 * r + 1) * NN + n] + __ldg(b2 + r);
    out[n] = o;
}

// ---------------- host ----------------
extern "C" void kernel_launch(void* const* d_in, const int* in_sizes, int n_in,
                              void* d_out, int out_size) {
    const float* x  = (const float*)d_in[0];
    const void*  src[3] = { d_in[1], d_in[3], d_in[5] };
    const void*  dst[3] = { d_in[2], d_in[4], d_in[6] };
    int          E[3]   = { in_sizes[1], in_sizes[3], in_sizes[5] };
    const float* W1 = (const float*)d_in[7];
    const float* b1 = (const float*)d_in[8];
    const float* W2 = (const float*)d_in[9];
    const float* b2 = (const float*)d_in[10];
    float*       out = (float*)d_out;

    int nprobe = E[0] < 2048 ? E[0] : 2048;
    k_detect<<<1, NT>>>((const unsigned*)d_in[1], nprobe);

    k_zero_cnt<<<(6 * NN + NT - 1) / NT, NT>>>();
    for (int r = 0; r < 3; r++)
        k_deg<<<(E[r] + NT - 1) / NT, NT>>>(src[r], dst[r], E[r], r);
    k_rsqrt<<<(6 * NN + NT - 1) / NT, NT>>>();

    k_layer1_node<<<(NN + NT - 1) / NT, NT>>>(x, W1);
    for (int r = 0; r < 3; r++) {
        long long work = (long long)E[r] * 4;
        int blocks = (int)((work + NT - 1) / NT);
        k_scatter16<<<blocks, NT>>>(src[r], dst[r], E[r], r * NN);
    }

    k_combine<<<(NN + NT - 1) / NT, NT>>>(b1, W2);
    for (int r = 0; r < 3; r++)
        k_scatter1<<<(E[r] + NT - 1) / NT, NT>>>(src[r], dst[r], E[r], r * NN);

    k_final<<<(NN + NT - 1) / NT, NT>>>(out, b2);
}